// round 15
// baseline (speedup 1.0000x reference)
#include <cuda_runtime.h>

// Fused SSIM loss. pred/target: [32,1,512,512] f32, WIN=11 VALID -> 502x502.
// out[0] = 1 - mean(S).
//
// R11 = R10 (barrier-free warp strips, shuffle halo, depth-2 prefetch) with
// the final-reduction bug fixed: R10's tree reduction assumed power-of-2 TPB
// and dropped dred[4] at stride 5->2 (lost ~6% of partials -> rel_err 1e-3).
// Now a guarded power-of-2 tree handles TPB=160 exactly.

#define BATCH   32
#define HH      512
#define WW      512
#define WIN     11
#define OHH     502
#define OWW     502
#define NBANDS  23
#define RPB     22
#define TPB     160
#define STRIDE  116     // output cols per warp (29 lanes * 4)
#define NBLK    (BATCH * NBANDS)   // 736

__device__ float        g_partial[NBLK];
__device__ unsigned int g_count = 0;

__global__ __launch_bounds__(TPB, 5) void ssim_main(const float* __restrict__ pred,
                                                    const float* __restrict__ targ,
                                                    float* __restrict__ out)
{
    const int band = blockIdx.x;
    const int img  = blockIdx.y;
    const int r0   = band * RPB;
    int rend = r0 + RPB - 1;
    if (rend > OHH - 1) rend = OHH - 1;

    const int t    = threadIdx.x;       // 0..159
    const int wid  = t >> 5;            // 0..4
    const int lane = t & 31;

    const int c_out = wid * STRIDE + lane * 4;          // logical output col
    const int c     = (c_out > 508) ? 508 : c_out;      // clamped load col

    __shared__ float  wsum[5];
    __shared__ int    is_last;
    __shared__ double dred[TPB];

    const float* pb = pred + img * (HH * WW);
    const float* qb = targ + img * (HH * WW);

    // Vertical sliding sums: s0=Sx, s1=Sy, s2=S(x^2+y^2), s3=Sxy.
    float s[4][4];
#pragma unroll
    for (int q = 0; q < 4; ++q)
#pragma unroll
        for (int j = 0; j < 4; ++j) s[q][j] = 0.f;

    // Warm-up: rows r0 .. r0+9.
    for (int rr = r0; rr < r0 + WIN - 1; ++rr) {
        const float4 p4 = *(const float4*)(pb + rr * WW + c);
        const float4 q4 = *(const float4*)(qb + rr * WW + c);
        const float pj[4] = {p4.x, p4.y, p4.z, p4.w};
        const float qj[4] = {q4.x, q4.y, q4.z, q4.w};
#pragma unroll
        for (int j = 0; j < 4; ++j) {
            s[0][j] += pj[j];
            s[1][j] += qj[j];
            s[2][j] = fmaf(pj[j], pj[j], fmaf(qj[j], qj[j], s[2][j]));
            s[3][j] = fmaf(pj[j], qj[j], s[3][j]);
        }
    }

    const float inv_np = 1.0f / 121.0f;
    const float k120   = 1.0f / 120.0f;     // cov_norm / NP
    const float cn     = 121.0f / 120.0f;   // cov_norm
    const float C1     = 1.0e-4f;
    const float C2     = 9.0e-4f;

    float acc = 0.0f;

    // Depth-2 pipeline prologue: rows r0+10 and r0+11 in flight.
    float4 pn  = *(const float4*)(pb + (r0 + WIN - 1) * WW + c);
    float4 qn  = *(const float4*)(qb + (r0 + WIN - 1) * WW + c);
    float4 pn2 = *(const float4*)(pb + (r0 + WIN) * WW + c);
    float4 qn2 = *(const float4*)(qb + (r0 + WIN) * WW + c);

    for (int orow = r0; orow <= rend; ++orow) {
        // Old top row (consumed at iteration end).
        const float4 po = *(const float4*)(pb + orow * WW + c);
        const float4 qo = *(const float4*)(qb + orow * WW + c);

        {   // add prefetched new row -> s covers rows orow..orow+10
            const float pj[4] = {pn.x, pn.y, pn.z, pn.w};
            const float qj[4] = {qn.x, qn.y, qn.z, qn.w};
#pragma unroll
            for (int j = 0; j < 4; ++j) {
                s[0][j] += pj[j];
                s[1][j] += qj[j];
                s[2][j] = fmaf(pj[j], pj[j], fmaf(qj[j], qj[j], s[2][j]));
                s[3][j] = fmaf(qj[j], pj[j], s[3][j]);
            }
        }

        // Rotate pipeline; issue distance-2 load (row orow+12, clamped).
        pn = pn2; qn = qn2;
        {
            int rnext2 = orow + WIN + 1;
            if (rnext2 > HH - 1) rnext2 = HH - 1;
            pn2 = *(const float4*)(pb + rnext2 * WW + c);
            qn2 = *(const float4*)(qb + rnext2 * WW + c);
        }

        // Horizontal 11-window via intra-warp shuffles (no barrier).
        // Window c..c+10 = own 4 + (t+1)'s 4 + (t+2)'s 4 - (t+2)'s col c+11.
        // Slide-ins: col c+11 = e0, c+12 = e1, c+13 = e2.
        float w[4], e0[4], e1[4], e2[4];
#pragma unroll
        for (int q = 0; q < 4; ++q) {
            const float h  = (s[q][0] + s[q][1]) + (s[q][2] + s[q][3]);
            const float h1 = __shfl_down_sync(0xffffffffu, h, 1);
            const float h2 = __shfl_down_sync(0xffffffffu, h, 2);
            e0[q] = __shfl_down_sync(0xffffffffu, s[q][3], 2);
            e1[q] = __shfl_down_sync(0xffffffffu, s[q][0], 3);
            e2[q] = __shfl_down_sync(0xffffffffu, s[q][1], 3);
            w[q] = (h + h1) + (h2 - e0[q]);
        }

#pragma unroll
        for (int j = 0; j < 4; ++j) {
            if (j) {
                const float* si = (j == 1) ? e0 : (j == 2) ? e1 : e2;
#pragma unroll
                for (int q = 0; q < 4; ++q)
                    w[q] = w[q] - s[q][j - 1] + si[q];
            }
            const float ux  = w[0] * inv_np;
            const float uy  = w[1] * inv_np;
            const float uxy = ux * uy;
            const float sq  = fmaf(ux, ux, uy * uy);
            const float A1  = fmaf(2.0f, uxy, C1);
            const float B1  = sq + C1;
            const float vxy = fmaf(w[3], k120, -cn * uxy);
            const float vs  = fmaf(w[2], k120, -cn * sq);   // vx + vy
            const float A2  = fmaf(2.0f, vxy, C2);
            const float B2  = vs + C2;
            const float S   = __fdividef(A1 * A2, B1 * B2);
            if (lane < 29 && c_out + j < OWW) acc += S;
        }

        {   // subtract old top row -> s covers orow+1..orow+10
            const float uj[4] = {po.x, po.y, po.z, po.w};
            const float vj[4] = {qo.x, qo.y, qo.z, qo.w};
#pragma unroll
            for (int j = 0; j < 4; ++j) {
                s[0][j] -= uj[j];
                s[1][j] -= vj[j];
                s[2][j] = fmaf(-uj[j], uj[j], fmaf(-vj[j], vj[j], s[2][j]));
                s[3][j] = fmaf(-vj[j], uj[j], s[3][j]);
            }
        }
    }

    // Block reduction (5 warps).
    float v = acc;
#pragma unroll
    for (int off = 16; off; off >>= 1)
        v += __shfl_xor_sync(0xffffffffu, v, off);
    if (lane == 0) wsum[wid] = v;
    __syncthreads();

    if (t == 0) {
        g_partial[img * NBANDS + band] =
            wsum[0] + wsum[1] + wsum[2] + wsum[3] + wsum[4];
        __threadfence();
        const unsigned int tick = atomicAdd(&g_count, 1u);
        is_last = (tick == NBLK - 1);
    }
    __syncthreads();

    // Last block performs the deterministic final reduction.
    // Guarded power-of-2 tree: correct for TPB=160 (non-power-of-2).
    if (is_last) {
        __threadfence();
        double sd = 0.0;
        for (int i = t; i < NBLK; i += TPB)   // fixed slots, fixed order
            sd += (double)g_partial[i];
        dred[t] = sd;
        __syncthreads();
#pragma unroll
        for (int st = 128; st > 0; st >>= 1) {
            if (t < st && t + st < TPB) dred[t] += dred[t + st];
            __syncthreads();
        }
        if (t == 0) {
            out[0] = (float)(1.0 - dred[0] / ((double)BATCH * OHH * OWW));
            g_count = 0;   // reset for next graph replay
        }
    }
}

extern "C" void kernel_launch(void* const* d_in, const int* in_sizes, int n_in,
                              void* d_out, int out_size)
{
    const float* pred = (const float*)d_in[0];
    const float* targ = (const float*)d_in[1];
    float* out = (float*)d_out;

    ssim_main<<<dim3(NBANDS, BATCH), TPB>>>(pred, targ, out);
}

// round 16
// speedup vs baseline: 1.5188x; 1.5188x over previous
#include <cuda_runtime.h>

// Fused SSIM loss. pred/target: [32,1,512,512] f32, WIN=11 VALID -> 502x502.
// out[0] = 1 - mean(S).
//
// R12 = R8 skeleton (smem staging, depth-2 prefetch, 1 barrier/row) with the
// vertical box-filter updates and SSIM math executed in PACKED f32x2
// (fma.rn.f32x2 / add.rn.f32x2 / mul.rn.f32x2) -> ~25% fewer instructions.
// R11 proved issue can reach 69% barrier-free but shuffles cost too many
// instructions; this keeps R8's instruction economy and halves the FP32 ops.

#define BATCH   32
#define HH      512
#define WW      512
#define WIN     11
#define OHH     502
#define OWW     502
#define NBANDS  28
#define RPB     18
#define TPB     128
#define NBLK    (BATCH * NBANDS)   // 896

#define SIGN2   0x8000000080000000ULL

typedef unsigned long long u64;

__device__ float        g_partial[NBLK];
__device__ unsigned int g_count = 0;

__device__ __forceinline__ u64 f2add(u64 a, u64 b) {
    u64 d; asm("add.rn.f32x2 %0, %1, %2;" : "=l"(d) : "l"(a), "l"(b)); return d;
}
__device__ __forceinline__ u64 f2mul(u64 a, u64 b) {
    u64 d; asm("mul.rn.f32x2 %0, %1, %2;" : "=l"(d) : "l"(a), "l"(b)); return d;
}
__device__ __forceinline__ u64 f2fma(u64 a, u64 b, u64 c) {
    u64 d; asm("fma.rn.f32x2 %0, %1, %2, %3;" : "=l"(d) : "l"(a), "l"(b), "l"(c)); return d;
}
__device__ __forceinline__ u64 pack2(float lo, float hi) {
    u64 d; asm("mov.b64 %0, {%1, %2};" : "=l"(d) : "r"(__float_as_uint(lo)), "r"(__float_as_uint(hi)));
    return d;
}
__device__ __forceinline__ void unpack2(u64 v, float& lo, float& hi) {
    unsigned int a, b;
    asm("mov.b64 {%0, %1}, %2;" : "=r"(a), "=r"(b) : "l"(v));
    lo = __uint_as_float(a); hi = __uint_as_float(b);
}
__device__ __forceinline__ u64 dup2(float x) {
    return pack2(x, x);
}

__global__ __launch_bounds__(TPB, 6) void ssim_main(const float* __restrict__ pred,
                                                    const float* __restrict__ targ,
                                                    float* __restrict__ out)
{
    const int band = blockIdx.x;
    const int img  = blockIdx.y;
    const int r0   = band * RPB;
    int rend = r0 + RPB - 1;
    if (rend > OHH - 1) rend = OHH - 1;

    const int t = threadIdx.x;          // 0..127
    const int c = t << 2;               // 4 cols per thread, c in [0,508]

    // Double-buffered staging of 4 vertical-sum rows (packed pairs stored as
    // 16B). Neighbor loads at t+1..t+3 consecutive -> conflict-free.
    __shared__ float4 sv[2][4][132];
    __shared__ float  wsum[4];
    __shared__ int    is_last;
    __shared__ double dred[TPB];

    {   // zero pads (idx 128..131)
        const float4 z4 = make_float4(0.f, 0.f, 0.f, 0.f);
        if (t < 32) {
            int b = t / 16, rem = t % 16;
            sv[b][rem / 4][128 + (rem & 3)] = z4;
        }
    }

    const float* pb = pred + img * (HH * WW);
    const float* qb = targ + img * (HH * WW);

    // Vertical sliding sums, PACKED pairs: [q][pair] where pair0=(c,c+1),
    // pair1=(c+2,c+3). q: 0=Sx, 1=Sy, 2=S(x^2+y^2), 3=Sxy.
    u64 s[4][2];
#pragma unroll
    for (int q = 0; q < 4; ++q) { s[q][0] = 0ULL; s[q][1] = 0ULL; }

    // Warm-up: rows r0 .. r0+9 (packed).
    for (int rr = r0; rr < r0 + WIN - 1; ++rr) {
        const double2 pd = *(const double2*)(pb + rr * WW + c);
        const double2 qd = *(const double2*)(qb + rr * WW + c);
        const u64 p2[2] = {__double_as_longlong(pd.x), __double_as_longlong(pd.y)};
        const u64 q2[2] = {__double_as_longlong(qd.x), __double_as_longlong(qd.y)};
#pragma unroll
        for (int h = 0; h < 2; ++h) {
            s[0][h] = f2add(s[0][h], p2[h]);
            s[1][h] = f2add(s[1][h], q2[h]);
            s[2][h] = f2fma(p2[h], p2[h], f2fma(q2[h], q2[h], s[2][h]));
            s[3][h] = f2fma(q2[h], p2[h], s[3][h]);
        }
    }

    const float inv_np = 1.0f / 121.0f;
    const float k120   = 1.0f / 120.0f;     // cov_norm / NP
    const float cn     = 121.0f / 120.0f;   // cov_norm
    const u64 inv2 = dup2(inv_np);
    const u64 k1202 = dup2(k120);
    const u64 ncn2 = dup2(-cn);
    const u64 two2 = dup2(2.0f);
    const u64 C1_2 = dup2(1.0e-4f);
    const u64 C2_2 = dup2(9.0e-4f);

    float acc = 0.0f;

    // Depth-2 pipeline prologue: rows r0+10 and r0+11 in flight (packed).
    double2 pnd  = *(const double2*)(pb + (r0 + WIN - 1) * WW + c);
    double2 qnd  = *(const double2*)(qb + (r0 + WIN - 1) * WW + c);
    double2 pnd2 = *(const double2*)(pb + (r0 + WIN) * WW + c);
    double2 qnd2 = *(const double2*)(qb + (r0 + WIN) * WW + c);

    for (int orow = r0; orow <= rend; ++orow) {
        const int par = orow & 1;

        // Old top row (consumed at iteration end).
        const double2 pod = *(const double2*)(pb + orow * WW + c);
        const double2 qod = *(const double2*)(qb + orow * WW + c);

        {   // add prefetched new row (packed)
            const u64 p2[2] = {__double_as_longlong(pnd.x), __double_as_longlong(pnd.y)};
            const u64 q2[2] = {__double_as_longlong(qnd.x), __double_as_longlong(qnd.y)};
#pragma unroll
            for (int h = 0; h < 2; ++h) {
                s[0][h] = f2add(s[0][h], p2[h]);
                s[1][h] = f2add(s[1][h], q2[h]);
                s[2][h] = f2fma(p2[h], p2[h], f2fma(q2[h], q2[h], s[2][h]));
                s[3][h] = f2fma(q2[h], p2[h], s[3][h]);
            }
        }

        // Stage vertical sums (same bit layout as 4 floats).
#pragma unroll
        for (int q = 0; q < 4; ++q) {
            double2 st;
            st.x = __longlong_as_double(s[q][0]);
            st.y = __longlong_as_double(s[q][1]);
            *(double2*)&sv[par][q][t] = st;
        }

        // Rotate pipeline; issue distance-2 load (row orow+12, clamped).
        pnd = pnd2; qnd = qnd2;
        {
            int rnext2 = orow + WIN + 1;
            if (rnext2 > HH - 1) rnext2 = HH - 1;
            pnd2 = *(const double2*)(pb + rnext2 * WW + c);
            qnd2 = *(const double2*)(qb + rnext2 * WW + c);
        }

        __syncthreads();

        // Horizontal 11-window sums (scalar sliding, as R8), then pack into
        // pairs W01=(w0,w1), W23=(w2,w3) for packed SSIM.
        u64 W01[4], W23[4];
#pragma unroll
        for (int q = 0; q < 4; ++q) {
            float sc0, sc1, sc2, sc3;
            unpack2(s[q][0], sc0, sc1);
            unpack2(s[q][1], sc2, sc3);
            const float4 n0 = sv[par][q][t + 1];
            const float4 n1 = sv[par][q][t + 2];
            const float4 n2 = sv[par][q][t + 3];
            const float w0 = ((sc0 + sc1) + (sc2 + sc3))
                           + ((n0.x + n0.y) + (n0.z + n0.w))
                           + ((n1.x + n1.y) + n1.z);        // cols c..c+10
            const float w1 = w0 - sc0 + n1.w;               // c+1..c+11
            const float w2 = w1 - sc1 + n2.x;               // c+2..c+12
            const float w3 = w2 - sc2 + n2.y;               // c+3..c+13
            W01[q] = pack2(w0, w1);
            W23[q] = pack2(w2, w3);
        }

        // Packed SSIM (2 pairs).
#pragma unroll
        for (int h = 0; h < 2; ++h) {
            const u64 wx  = h ? W23[0] : W01[0];
            const u64 wy  = h ? W23[1] : W01[1];
            const u64 wss = h ? W23[2] : W01[2];
            const u64 wxy = h ? W23[3] : W01[3];
            const u64 ux  = f2mul(wx, inv2);
            const u64 uy  = f2mul(wy, inv2);
            const u64 uxy = f2mul(ux, uy);
            const u64 sq  = f2fma(ux, ux, f2mul(uy, uy));
            const u64 A1  = f2fma(two2, uxy, C1_2);
            const u64 B1  = f2add(sq, C1_2);
            const u64 vxy = f2fma(wxy, k1202, f2mul(uxy, ncn2));
            const u64 vs  = f2fma(wss, k1202, f2mul(sq, ncn2));   // vx+vy
            const u64 A2  = f2fma(two2, vxy, C2_2);
            const u64 B2  = f2add(vs, C2_2);
            const u64 num = f2mul(A1, A2);
            const u64 den = f2mul(B1, B2);
            float n_lo, n_hi, d_lo, d_hi;
            unpack2(num, n_lo, n_hi);
            unpack2(den, d_lo, d_hi);
            const float S0 = __fdividef(n_lo, d_lo);
            const float S1 = __fdividef(n_hi, d_hi);
            const int col = c + 2 * h;
            if (col < OWW)     acc += S0;
            if (col + 1 < OWW) acc += S1;
        }

        {   // subtract old top row (packed; negate via sign-bit XOR)
            const u64 p2[2] = {__double_as_longlong(pod.x), __double_as_longlong(pod.y)};
            const u64 q2[2] = {__double_as_longlong(qod.x), __double_as_longlong(qod.y)};
#pragma unroll
            for (int h = 0; h < 2; ++h) {
                const u64 np = p2[h] ^ SIGN2;
                const u64 nq = q2[h] ^ SIGN2;
                s[0][h] = f2add(s[0][h], np);
                s[1][h] = f2add(s[1][h], nq);
                s[2][h] = f2fma(np, p2[h], f2fma(nq, q2[h], s[2][h]));
                s[3][h] = f2fma(nq, p2[h], s[3][h]);
            }
        }
    }

    // Block reduction (4 warps).
    float v = acc;
#pragma unroll
    for (int off = 16; off; off >>= 1)
        v += __shfl_xor_sync(0xffffffffu, v, off);
    const int lane = t & 31, wid = t >> 5;
    if (lane == 0) wsum[wid] = v;
    __syncthreads();

    if (t == 0) {
        g_partial[img * NBANDS + band] = wsum[0] + wsum[1] + wsum[2] + wsum[3];
        __threadfence();
        const unsigned int tick = atomicAdd(&g_count, 1u);
        is_last = (tick == NBLK - 1);
    }
    __syncthreads();

    // Last block performs the deterministic final reduction.
    if (is_last) {
        __threadfence();
        double sd = 0.0;
        for (int i = t; i < NBLK; i += TPB)   // fixed slots, fixed order
            sd += (double)g_partial[i];
        dred[t] = sd;
        __syncthreads();
#pragma unroll
        for (int st = TPB / 2; st > 0; st >>= 1) {
            if (t < st) dred[t] += dred[t + st];
            __syncthreads();
        }
        if (t == 0) {
            out[0] = (float)(1.0 - dred[0] / ((double)BATCH * OHH * OWW));
            g_count = 0;   // reset for next graph replay
        }
    }
}

extern "C" void kernel_launch(void* const* d_in, const int* in_sizes, int n_in,
                              void* d_out, int out_size)
{
    const float* pred = (const float*)d_in[0];
    const float* targ = (const float*)d_in[1];
    float* out = (float*)d_out;

    ssim_main<<<dim3(NBANDS, BATCH), TPB>>>(pred, targ, out);
}